// round 4
// baseline (speedup 1.0000x reference)
#include <cuda_runtime.h>

// FeatureSim: attn[b,i,j] = softmax_j( sum_k w[k]*|x[b,i,k]-x[b,j,k]| ), mask j < len[b].
// B=8, L=1024, F=16 (first 11 used), out f32 [8,1024,1024].
//
// R4 (= R3 with the __exp2f compile fix -> inline ex2.approx.f32):
//     - grid 1024 (BQ=8) to fix 3-blocks/SM wave quantization tail.
//     - features pre-scaled y = x*|w_k|*log2(e): exp -> single ex2.approx MUFU,
//       loop accumulate -> add.f32x2 (no weight operand needed in loop).
//     - sign of w folded via single LOP3 per half: (d & 0x7FFFFFFF) ^ m_k.
//     - key-mask folded into accumulator init (bias -1e30 -> ex2 -> exact 0): no SELs.
//     - no per-row shuffles: row sums reduced warp-per-row from the smem e-slab
//       after one barrier. 3 barriers per block total.

#define L_SEQ 1024
#define FDIM  16
#define NF    11
#define BQ    8             // rows per block
#define TPB   256           // each thread owns 4 consecutive key columns (2 f32x2 pairs)
#define BPB   (L_SEQ / BQ)  // 128 blocks per batch

typedef unsigned long long u64;

__device__ __forceinline__ u64 pack2(float lo, float hi) {
    u64 r; asm("mov.b64 %0, {%1, %2};" : "=l"(r) : "f"(lo), "f"(hi)); return r;
}
__device__ __forceinline__ void unpack2(u64 v, float& lo, float& hi) {
    asm("mov.b64 {%0, %1}, %2;" : "=f"(lo), "=f"(hi) : "l"(v));
}
__device__ __forceinline__ u64 add2(u64 a, u64 b) {
    u64 r; asm("add.rn.f32x2 %0, %1, %2;" : "=l"(r) : "l"(a), "l"(b)); return r;
}
// t = sgn * |d| per packed half: one LOP3 per 32 bits: (d & 0x7FFFFFFF) ^ m
__device__ __forceinline__ u64 abssign2(u64 d, unsigned m) {
    unsigned lo, hi;
    asm("mov.b64 {%0, %1}, %2;" : "=r"(lo), "=r"(hi) : "l"(d));
    lo = (lo & 0x7fffffffu) ^ m;
    hi = (hi & 0x7fffffffu) ^ m;
    u64 r; asm("mov.b64 %0, {%1, %2};" : "=l"(r) : "r"(lo), "r"(hi));
    return r;
}
__device__ __forceinline__ float ex2(float a) {
    float r; asm("ex2.approx.f32 %0, %1;" : "=f"(r) : "f"(a)); return r;
}

#define LOG2E 1.4426950408889634f

__global__ __launch_bounds__(TPB)
void featsim_kernel(const float* __restrict__ x,
                    const int*   __restrict__ lens,
                    const float* __restrict__ w,
                    float*       __restrict__ out)
{
    const int b    = blockIdx.x / BPB;
    const int rb   = blockIdx.x % BPB;
    const int i0   = rb * BQ;
    const int tid  = threadIdx.x;
    const int lane = tid & 31;
    const int warp = tid >> 5;
    const int j0   = tid * 4;

    __shared__ u64 sq2[BQ][NF];                        // scaled queries, duplicated {y,y}
    __shared__ __align__(16) float se[BQ][L_SEQ];      // unnormalized e staging (32 KB)
    __shared__ float red[BQ];                          // per-row 1/sum

    // Per-feature: positive scale wl_k = |w_k|*log2e, sign mask m_k.
    unsigned m[NF];
    float wl[NF];
#pragma unroll
    for (int k = 0; k < NF; ++k) {
        float wk = w[k];                               // broadcast LDG, L2-resident
        m[k]  = __float_as_uint(wk) & 0x80000000u;
        wl[k] = fabsf(wk) * LOG2E;
    }

    // Stage scaled queries: sq2[r][k] = {y, y}, y = x*wl_k.
    if (tid < BQ * NF) {
        int r = tid / NF, k = tid - r * NF;
        float y = x[(size_t)(b * L_SEQ + i0 + r) * FDIM + k] * wl[k];
        sq2[r][k] = pack2(y, y);
    }

    // Keys: 4 cols -> pre-negated scaled pairs nk[p][k] = {-y(col 2p), -y(col 2p+1)}.
    float kr[4][NF];
#pragma unroll
    for (int cc = 0; cc < 4; ++cc) {
        const float4* kp = reinterpret_cast<const float4*>(
            x + (size_t)(b * L_SEQ + j0 + cc) * FDIM);
        float4 a = kp[0], c = kp[1], d = kp[2];
        kr[cc][0] = a.x;  kr[cc][1] = a.y;  kr[cc][2]  = a.z;  kr[cc][3] = a.w;
        kr[cc][4] = c.x;  kr[cc][5] = c.y;  kr[cc][6]  = c.z;  kr[cc][7] = c.w;
        kr[cc][8] = d.x;  kr[cc][9] = d.y;  kr[cc][10] = d.z;
    }
    u64 nk0[NF], nk1[NF];
#pragma unroll
    for (int k = 0; k < NF; ++k) {
        float nw = -wl[k];
        nk0[k] = pack2(kr[0][k] * nw, kr[1][k] * nw);
        nk1[k] = pack2(kr[2][k] * nw, kr[3][k] * nw);
    }

    // Key-mask as accumulator bias: invalid col -> -1e30 -> ex2 -> 0 exactly.
    const int len = lens[b];
    const u64 bias0 = pack2((j0 + 0 < len) ? 0.f : -1e30f,
                            (j0 + 1 < len) ? 0.f : -1e30f);
    const u64 bias1 = pack2((j0 + 2 < len) ? 0.f : -1e30f,
                            (j0 + 3 < len) ? 0.f : -1e30f);

    __syncthreads();

    // ---- main loop: scores in log2 units, e staged to smem ----
#pragma unroll
    for (int r = 0; r < BQ; ++r) {
        u64 s0 = bias0, s1 = bias1;
#pragma unroll
        for (int k = 0; k < NF; ++k) {
            u64 qq = sq2[r][k];                        // LDS.64 broadcast
            s0 = add2(s0, abssign2(add2(qq, nk0[k]), m[k]));
            s1 = add2(s1, abssign2(add2(qq, nk1[k]), m[k]));
        }
        float f0, f1, f2, f3;
        unpack2(s0, f0, f1);
        unpack2(s1, f2, f3);
        *reinterpret_cast<float4*>(&se[r][j0]) =
            make_float4(ex2(f0), ex2(f1), ex2(f2), ex2(f3));
    }
    __syncthreads();

    // ---- row sums: warp w reduces row w straight from the e-slab ----
    {
        float acc = 0.f;
#pragma unroll
        for (int p = 0; p < 8; ++p) {
            float4 v = *reinterpret_cast<float4*>(&se[warp][lane * 4 + p * 128]);
            acc += (v.x + v.y) + (v.z + v.w);
        }
#pragma unroll
        for (int o = 16; o > 0; o >>= 1)
            acc += __shfl_xor_sync(0xffffffffu, acc, o);
        if (lane == 0) {
            float inv; asm("rcp.approx.f32 %0, %1;" : "=f"(inv) : "f"(acc));
            red[warp] = inv;                           // len>=1 => acc>0
        }
    }
    __syncthreads();

    // ---- normalize + store ----
    float4* outb = reinterpret_cast<float4*>(out) + (size_t)(b * L_SEQ + i0) * (L_SEQ / 4);
#pragma unroll
    for (int r = 0; r < BQ; ++r) {
        float inv = red[r];
        float4 ev = *reinterpret_cast<float4*>(&se[r][j0]);
        outb[(size_t)r * (L_SEQ / 4) + tid] =
            make_float4(ev.x * inv, ev.y * inv, ev.z * inv, ev.w * inv);
    }
}

extern "C" void kernel_launch(void* const* d_in, const int* in_sizes, int n_in,
                              void* d_out, int out_size)
{
    const float* x    = (const float*)d_in[0];   // [8,1024,16] f32
    const int*   lens = (const int*)d_in[1];     // [8] i32
    const float* w    = (const float*)d_in[2];   // [11] f32
    float*       out  = (float*)d_out;           // [8,1024,1024] f32

    dim3 grid(8 * BPB);   // 1024 blocks
    dim3 block(TPB);
    featsim_kernel<<<grid, block>>>(x, lens, w, out);
}

// round 5
// speedup vs baseline: 1.0647x; 1.0647x over previous
#include <cuda_runtime.h>

// FeatureSim: attn[b,i,j] = softmax_j( sum_k w[k]*|x[b,i,k]-x[b,j,k]| ), mask j < len[b].
// B=8, L=1024, F=16 (first 11 used), out f32 [8,1024,1024].
//
// R5: - single fused LOP3 per half for sgn*|d|: (h & 0x7fffffff) ^ m  (was AND+XOR).
//     - LDS.128 paired query broadcasts (5x ulonglong2 + 1x u64 per row, was 11 LDS.64).
//     - 4-way accumulator split for ILP (chain 6 deep instead of 11).
//     - __launch_bounds__(256,3): pin 3 blocks/SM (regs <= 85); R4's 86 regs dropped
//       occupancy to 2 blocks/SM and regressed.
//     - kept from R3/R4: y = x*|w|*log2e prescale (exp = one ex2.approx MUFU),
//       mask as -1e30 accumulator bias, warp-per-row smem reduction, 3 barriers total.

#define L_SEQ 1024
#define FDIM  16
#define NF    11
#define BQ    8             // rows per block
#define TPB   256           // each thread owns 4 consecutive key columns (2 f32x2 pairs)
#define BPB   (L_SEQ / BQ)  // 128 blocks per batch

typedef unsigned long long u64;
typedef unsigned int u32;

__device__ __forceinline__ u64 pack2(float lo, float hi) {
    u64 r; asm("mov.b64 %0, {%1, %2};" : "=l"(r) : "f"(lo), "f"(hi)); return r;
}
__device__ __forceinline__ void unpack2(u64 v, float& lo, float& hi) {
    asm("mov.b64 {%0, %1}, %2;" : "=f"(lo), "=f"(hi) : "l"(v));
}
__device__ __forceinline__ u64 add2(u64 a, u64 b) {
    u64 r; asm("add.rn.f32x2 %0, %1, %2;" : "=l"(r) : "l"(a), "l"(b)); return r;
}
__device__ __forceinline__ float ex2(float a) {
    float r; asm("ex2.approx.f32 %0, %1;" : "=f"(r) : "f"(a)); return r;
}
// sgn*|d| per packed half: ONE LOP3 per 32-bit half: (h & 0x7fffffff) ^ m
__device__ __forceinline__ u64 abssign2(u64 d, u32 m) {
    union { u64 u; uint2 v; } c; c.u = d;
    c.v.x = (c.v.x & 0x7fffffffu) ^ m;
    c.v.y = (c.v.y & 0x7fffffffu) ^ m;
    return c.u;
}

#define LOG2E 1.4426950408889634f

__global__ __launch_bounds__(TPB, 3)
void featsim_kernel(const float* __restrict__ x,
                    const int*   __restrict__ lens,
                    const float* __restrict__ w,
                    float*       __restrict__ out)
{
    const int b    = blockIdx.x / BPB;
    const int rb   = blockIdx.x % BPB;
    const int i0   = rb * BQ;
    const int tid  = threadIdx.x;
    const int lane = tid & 31;
    const int warp = tid >> 5;
    const int j0   = tid * 4;

    __shared__ __align__(16) u64 sq2[BQ][12];          // scaled queries {y,y}; [11] pad unused
    __shared__ __align__(16) float se[BQ][L_SEQ];      // unnormalized e staging (32 KB)
    __shared__ float red[BQ];                          // per-row 1/sum

    // Per-feature: positive scale wl_k = |w_k|*log2e, sign mask m_k.
    u32 m[NF];
    float wl[NF];
#pragma unroll
    for (int k = 0; k < NF; ++k) {
        float wk = w[k];
        m[k]  = __float_as_uint(wk) & 0x80000000u;
        wl[k] = fabsf(wk) * LOG2E;
    }

    // Stage scaled queries: sq2[r][k] = {y, y}, y = x*wl_k.
    if (tid < BQ * NF) {
        int r = tid / NF, k = tid - r * NF;
        float y = x[(size_t)(b * L_SEQ + i0 + r) * FDIM + k] * wl[k];
        sq2[r][k] = pack2(y, y);
    }

    // Keys: 4 cols -> pre-negated scaled pairs.
    float kr[4][NF];
#pragma unroll
    for (int cc = 0; cc < 4; ++cc) {
        const float4* kp = reinterpret_cast<const float4*>(
            x + (size_t)(b * L_SEQ + j0 + cc) * FDIM);
        float4 a = kp[0], c = kp[1], d = kp[2];
        kr[cc][0] = a.x;  kr[cc][1] = a.y;  kr[cc][2]  = a.z;  kr[cc][3] = a.w;
        kr[cc][4] = c.x;  kr[cc][5] = c.y;  kr[cc][6]  = c.z;  kr[cc][7] = c.w;
        kr[cc][8] = d.x;  kr[cc][9] = d.y;  kr[cc][10] = d.z;
    }
    u64 nk0[NF], nk1[NF];
#pragma unroll
    for (int k = 0; k < NF; ++k) {
        float nw = -wl[k];
        nk0[k] = pack2(kr[0][k] * nw, kr[1][k] * nw);
        nk1[k] = pack2(kr[2][k] * nw, kr[3][k] * nw);
    }

    // Key-mask as accumulator bias: invalid col -> -1e30 -> ex2 -> exact 0.
    const int len = lens[b];
    const u64 bias0 = pack2((j0 + 0 < len) ? 0.f : -1e30f,
                            (j0 + 1 < len) ? 0.f : -1e30f);
    const u64 bias1 = pack2((j0 + 2 < len) ? 0.f : -1e30f,
                            (j0 + 3 < len) ? 0.f : -1e30f);

    __syncthreads();

    // ---- main loop: scores in log2 units, e staged to smem ----
#pragma unroll
    for (int r = 0; r < BQ; ++r) {
        const ulonglong2* qp = reinterpret_cast<const ulonglong2*>(sq2[r]);
        u64 sa0 = bias0, sb0 = 0ULL;    // split accumulators: even/odd k
        u64 sa1 = bias1, sb1 = 0ULL;
#pragma unroll
        for (int kk = 0; kk < 5; ++kk) {
            ulonglong2 q = qp[kk];                     // LDS.128 broadcast (k=2kk, 2kk+1)
            const int k0 = 2 * kk, k1 = 2 * kk + 1;
            sa0 = add2(sa0, abssign2(add2(q.x, nk0[k0]), m[k0]));
            sa1 = add2(sa1, abssign2(add2(q.x, nk1[k0]), m[k0]));
            sb0 = add2(sb0, abssign2(add2(q.y, nk0[k1]), m[k1]));
            sb1 = add2(sb1, abssign2(add2(q.y, nk1[k1]), m[k1]));
        }
        {   // tail feature k=10 (LDS.64 broadcast)
            u64 q = sq2[r][10];
            sa0 = add2(sa0, abssign2(add2(q, nk0[10]), m[10]));
            sa1 = add2(sa1, abssign2(add2(q, nk1[10]), m[10]));
        }
        u64 s0 = add2(sa0, sb0);
        u64 s1 = add2(sa1, sb1);

        float f0, f1, f2, f3;
        unpack2(s0, f0, f1);
        unpack2(s1, f2, f3);
        *reinterpret_cast<float4*>(&se[r][j0]) =
            make_float4(ex2(f0), ex2(f1), ex2(f2), ex2(f3));
    }
    __syncthreads();

    // ---- row sums: warp w reduces row w straight from the e-slab ----
    {
        float acc = 0.f;
#pragma unroll
        for (int p = 0; p < 8; ++p) {
            float4 v = *reinterpret_cast<float4*>(&se[warp][lane * 4 + p * 128]);
            acc += (v.x + v.y) + (v.z + v.w);
        }
#pragma unroll
        for (int o = 16; o > 0; o >>= 1)
            acc += __shfl_xor_sync(0xffffffffu, acc, o);
        if (lane == 0) {
            float inv; asm("rcp.approx.f32 %0, %1;" : "=f"(inv) : "f"(acc));
            red[warp] = inv;                           // len>=1 => acc>0
        }
    }
    __syncthreads();

    // ---- normalize + store ----
    float4* outb = reinterpret_cast<float4*>(out) + (size_t)(b * L_SEQ + i0) * (L_SEQ / 4);
#pragma unroll
    for (int r = 0; r < BQ; ++r) {
        float inv = red[r];
        float4 ev = *reinterpret_cast<float4*>(&se[r][j0]);
        outb[(size_t)r * (L_SEQ / 4) + tid] =
            make_float4(ev.x * inv, ev.y * inv, ev.z * inv, ev.w * inv);
    }
}

extern "C" void kernel_launch(void* const* d_in, const int* in_sizes, int n_in,
                              void* d_out, int out_size)
{
    const float* x    = (const float*)d_in[0];   // [8,1024,16] f32
    const int*   lens = (const int*)d_in[1];     // [8] i32
    const float* w    = (const float*)d_in[2];   // [11] f32
    float*       out  = (float*)d_out;           // [8,1024,1024] f32

    dim3 grid(8 * BPB);   // 1024 blocks
    dim3 block(TPB);
    featsim_kernel<<<grid, block>>>(x, lens, w, out);
}